// round 9
// baseline (speedup 1.0000x reference)
#include <cuda_runtime.h>
#include <cuda_bf16.h>
#include <cuda_fp16.h>
#include <cstdint>

// Problem shape (fixed for this dataset variant)
#define NNODES 50000
#define NEDGES 800000
#define IN_DIM 256
#define KHEADS 4
#define FDIM   64
#define KF     256   // KHEADS * FDIM == IN_DIM here

// Scratch (device globals: allocation-free per harness rules)
__device__ __half         g_nodefeat_h[(size_t)NNODES * KF];  // [N, 256] fp16 ([K][F] cols)
__device__ float4         g_gauss[NEDGES];                    // [E, 4]
__device__ __nv_bfloat16  g_w_hi[KF * IN_DIM];                // W bf16 hi
__device__ __nv_bfloat16  g_w_lo[KF * IN_DIM];                // W bf16 lo

// ===========================================================================
// Helpers (family-common PTX only: ldmatrix + mma.sync, no tcgen05)
// ===========================================================================
__device__ __forceinline__ uint32_t smem_to_u32(const void* p) {
    uint32_t a;
    asm("{ .reg .u64 t; cvta.to.shared.u64 t, %1; cvt.u32.u64 %0, t; }"
        : "=r"(a) : "l"(p));
    return a;
}

__device__ __forceinline__ void ldmatrix_x4(uint32_t* r, uint32_t addr) {
    asm volatile("ldmatrix.sync.aligned.m8n8.x4.shared.b16 {%0,%1,%2,%3}, [%4];"
        : "=r"(r[0]), "=r"(r[1]), "=r"(r[2]), "=r"(r[3]) : "r"(addr));
}

__device__ __forceinline__ void mma_bf16(float* d, const uint32_t* a,
                                         uint32_t b0, uint32_t b1) {
    asm volatile(
        "mma.sync.aligned.m16n8k16.row.col.f32.bf16.bf16.f32 "
        "{%0,%1,%2,%3}, {%4,%5,%6,%7}, {%8,%9}, {%0,%1,%2,%3};"
        : "+f"(d[0]), "+f"(d[1]), "+f"(d[2]), "+f"(d[3])
        : "r"(a[0]), "r"(a[1]), "r"(a[2]), "r"(a[3]), "r"(b0), "r"(b1));
}

__device__ __forceinline__ uint32_t pack2(__nv_bfloat16 x, __nv_bfloat16 y) {
    uint16_t lo = *(uint16_t*)&x, hi = *(uint16_t*)&y;
    return (uint32_t)lo | ((uint32_t)hi << 16);
}

// ===========================================================================
// Kernel W: one-time W pre-conversion fp32 -> bf16 hi/lo (row-major layout)
// ===========================================================================
__global__ void wconv_kernel(const float* __restrict__ W)
{
    const int i = blockIdx.x * blockDim.x + threadIdx.x;   // float4 index
    if (i >= (KF * IN_DIM) / 4) return;
    const float4 v = ((const float4*)W)[i];
    const float* f = (const float*)&v;
    __nv_bfloat16 h[4], l[4];
#pragma unroll
    for (int q = 0; q < 4; q++) {
        h[q] = __float2bfloat16_rn(f[q]);
        l[q] = __float2bfloat16_rn(f[q] - __bfloat162float(h[q]));
    }
    ((uint2*)g_w_hi)[i] = make_uint2(pack2(h[0], h[1]), pack2(h[2], h[3]));
    ((uint2*)g_w_lo)[i] = make_uint2(pack2(l[0], l[1]), pack2(l[2], l[3]));
}

// ===========================================================================
// Kernel A: bf16 3x-split tensor-core GEMM  (unchanged from R7, 131us best)
// ===========================================================================
#define BK 64
#define LDS_ROW 72                       // elems (144 bytes)
#define TILE_BYTES (128 * LDS_ROW * 2)   // 18432 per hi or lo
#define GEMM_SMEM (4 * TILE_BYTES)       // 73728

__global__ __launch_bounds__(256, 2)
void gemm_mma_kernel(const float* __restrict__ A, __half* __restrict__ C, int M)
{
    extern __shared__ char smem[];
    const uint32_t sb   = smem_to_u32(smem);
    const uint32_t sA_h = sb;
    const uint32_t sA_l = sb + TILE_BYTES;
    const uint32_t sW_h = sb + 2 * TILE_BYTES;
    const uint32_t sW_l = sb + 3 * TILE_BYTES;

    const int tid  = threadIdx.x;
    const int wid  = tid >> 5;
    const int lane = tid & 31;
    const int m0   = blockIdx.x * 128;
    const int bn   = blockIdx.y * 128;

    const int wm = wid & 1;      // m half (64)
    const int wn = wid >> 1;     // n quarter (32)

    float acc[4][4][4];
#pragma unroll
    for (int i = 0; i < 4; i++)
#pragma unroll
        for (int j = 0; j < 4; j++)
#pragma unroll
            for (int q = 0; q < 4; q++) acc[i][j][q] = 0.0f;

    for (int c = 0; c < IN_DIM / BK; c++) {
        const int kc = c * BK;

        __syncthreads();   // previous chunk's compute readers done

        // ---- A: load fp32, split to bf16 hi/lo, store. 128x64 = 2048 float4 ----
#pragma unroll
        for (int j = 0; j < 8; j++) {
            const int id  = tid + j * 256;
            const int row = id >> 4;
            const int c4  = (id & 15) * 4;
            const int gm  = m0 + row;

            float4 a = (gm < M)
                ? *(const float4*)(A + (size_t)gm * IN_DIM + kc + c4)
                : make_float4(0.f, 0.f, 0.f, 0.f);

            const float* av = (const float*)&a;
            __nv_bfloat16 ah[4], al[4];
#pragma unroll
            for (int q = 0; q < 4; q++) {
                ah[q] = __float2bfloat16_rn(av[q]);
                al[q] = __float2bfloat16_rn(av[q] - __bfloat162float(ah[q]));
            }
            const uint32_t off = (uint32_t)(row * (LDS_ROW * 2) + c4 * 2);
            asm volatile("st.shared.v2.b32 [%0], {%1,%2};" ::
                "r"(sA_h + off), "r"(pack2(ah[0], ah[1])), "r"(pack2(ah[2], ah[3])) : "memory");
            asm volatile("st.shared.v2.b32 [%0], {%1,%2};" ::
                "r"(sA_l + off), "r"(pack2(al[0], al[1])), "r"(pack2(al[2], al[3])) : "memory");
        }
        // ---- W: pre-converted bf16, straight 16B LDG -> STS. 128x64 bf16 ----
#pragma unroll
        for (int j = 0; j < 4; j++) {
            const int id  = tid + j * 256;        // 0..1023
            const int row = id >> 3;              // 0..127
            const int c8  = (id & 7) * 8;         // bf16 col in chunk
            const size_t goff = (size_t)(bn + row) * IN_DIM + kc + c8;
            const uint4 wh = *(const uint4*)(g_w_hi + goff);
            const uint4 wl = *(const uint4*)(g_w_lo + goff);
            const uint32_t off = (uint32_t)(row * (LDS_ROW * 2) + c8 * 2);
            asm volatile("st.shared.v4.b32 [%0], {%1,%2,%3,%4};" ::
                "r"(sW_h + off), "r"(wh.x), "r"(wh.y), "r"(wh.z), "r"(wh.w) : "memory");
            asm volatile("st.shared.v4.b32 [%0], {%1,%2,%3,%4};" ::
                "r"(sW_l + off), "r"(wl.x), "r"(wl.y), "r"(wl.z), "r"(wl.w) : "memory");
        }
        __syncthreads();

        // ---- compute: 4 k16 steps ----
#pragma unroll
        for (int ks = 0; ks < 4; ks++) {
            const int k16 = ks * 16;
            const uint32_t kbyte = (uint32_t)((k16 + (lane >> 4) * 8) * 2);

            uint32_t a_h[4][4], a_l[4][4];
#pragma unroll
            for (int mt = 0; mt < 4; mt++) {
                const uint32_t roff =
                    (uint32_t)((wm * 64 + mt * 16 + (lane & 15)) * (LDS_ROW * 2)) + kbyte;
                ldmatrix_x4(a_h[mt], sA_h + roff);
                ldmatrix_x4(a_l[mt], sA_l + roff);
            }
            uint32_t b_h[2][4], b_l[2][4];
#pragma unroll
            for (int bg = 0; bg < 2; bg++) {
                const uint32_t roff =
                    (uint32_t)((wn * 32 + bg * 16 + (lane & 15)) * (LDS_ROW * 2)) + kbyte;
                ldmatrix_x4(b_h[bg], sW_h + roff);
                ldmatrix_x4(b_l[bg], sW_l + roff);
            }

#pragma unroll
            for (int mt = 0; mt < 4; mt++) {
#pragma unroll
                for (int nt = 0; nt < 4; nt++) {
                    const int bg = nt >> 1, sel = nt & 1;
                    const uint32_t bh0 = b_h[bg][sel], bh1 = b_h[bg][sel + 2];
                    const uint32_t bl0 = b_l[bg][sel], bl1 = b_l[bg][sel + 2];
                    mma_bf16(acc[mt][nt], a_h[mt], bh0, bh1);   // hh
                    mma_bf16(acc[mt][nt], a_h[mt], bl0, bl1);   // hl
                    mma_bf16(acc[mt][nt], a_l[mt], bh0, bh1);   // lh
                }
            }
        }
    }

    // ---- epilogue: fragment -> gmem fp16 ----
    const int qrow = lane >> 2;
    const int qcol = (lane & 3) * 2;
#pragma unroll
    for (int mt = 0; mt < 4; mt++) {
        const int r0 = m0 + wm * 64 + mt * 16 + qrow;
#pragma unroll
        for (int nt = 0; nt < 4; nt++) {
            const int col = bn + wn * 32 + nt * 8 + qcol;
            if (r0 < M)
                *(__half2*)(C + (size_t)r0 * KF + col) =
                    __floats2half2_rn(acc[mt][nt][0], acc[mt][nt][1]);
            if (r0 + 8 < M)
                *(__half2*)(C + (size_t)(r0 + 8) * KF + col) =
                    __floats2half2_rn(acc[mt][nt][2], acc[mt][nt][3]);
        }
    }
}

// ---------------------------------------------------------------------------
// Kernel B: per-edge gaussian weights
// ---------------------------------------------------------------------------
__global__ void gauss_kernel(const float* __restrict__ pseudo,
                             const float* __restrict__ mu,
                             const float* __restrict__ inv_sigma,
                             int E)
{
    const int i = blockIdx.x * blockDim.x + threadIdx.x;
    if (i >= E) return;
    const float2 p = *(const float2*)(pseudo + 2 * (size_t)i);

    float w[4];
#pragma unroll
    for (int k = 0; k < 4; k++) {
        const float dx = p.x - mu[2 * k + 0];
        const float dy = p.y - mu[2 * k + 1];
        const float sx = inv_sigma[2 * k + 0];
        const float sy = inv_sigma[2 * k + 1];
        const float t  = dx * dx * sx * sx + dy * dy * sy * sy;
        w[k] = expf(-0.5f * t);
    }
    g_gauss[i] = make_float4(w[0], w[1], w[2], w[3]);
}

// ---------------------------------------------------------------------------
// Kernel I: out[n, f] = bias[f]  (pre-fill so agg can atomically accumulate)
// ---------------------------------------------------------------------------
__global__ void init_out_kernel(const float* __restrict__ bias,
                                float* __restrict__ out, int N)
{
    const int i = blockIdx.x * blockDim.x + threadIdx.x;   // float4 index
    if (i >= N * (FDIM / 4)) return;
    ((float4*)out)[i] = ((const float4*)bias)[i & (FDIM / 4 - 1)];
}

// ---------------------------------------------------------------------------
// Kernel C: EDGE-BALANCED weighted gather + reduce.
// Each warp owns exactly EPW consecutive edges (uniform work). One binary
// search per warp locates the starting row; row boundaries are then walked
// forward via uniform scalar rowptr reads. Partial row sums flush via
// atomicAdd into the bias-prefilled output. Loads are the known-good R7
// pattern (4x coalesced half2 per edge per lane), front-batched 4 edges deep.
// ---------------------------------------------------------------------------
#define EPW 64

__global__ void agg_kernel(const int* __restrict__ rowptr,
                           const int* __restrict__ colind,
                           float* __restrict__ out, int N, int E)
{
    const int warp = (blockIdx.x * blockDim.x + threadIdx.x) >> 5;
    const int lane = threadIdx.x & 31;
    const int base = warp * EPW;
    if (base >= E) return;
    const int end = min(base + EPW, E);

    // binary search: largest r with rowptr[r] <= base  (rowptr[0]=0 <= base)
    int lo = 0, hi = N - 1;
    while (lo < hi) {
        const int mid = (lo + hi + 1) >> 1;
        if (rowptr[mid] <= base) lo = mid; else hi = mid - 1;
    }
    int cur = lo;
    int nb  = rowptr[cur + 1];

    const __half* __restrict__ X = g_nodefeat_h;
    const int foff = 2 * lane;
    float ax = 0.f, ay = 0.f;
    bool dirty = false;

    int e = base;
    while (e < end) {
        const int gcount = min(4, end - e);
        float4 w[4];
        float2 v[4][4];
#pragma unroll
        for (int q = 0; q < 4; q++) {
            if (q < gcount) {
                const int s = colind[e + q];
                w[q] = g_gauss[e + q];
                const __half* b = X + (size_t)s * KF + foff;
                v[q][0] = __half22float2(*(const __half2*)(b + 0));
                v[q][1] = __half22float2(*(const __half2*)(b + 64));
                v[q][2] = __half22float2(*(const __half2*)(b + 128));
                v[q][3] = __half22float2(*(const __half2*)(b + 192));
            }
        }
#pragma unroll
        for (int q = 0; q < 4; q++) {
            if (q >= gcount) break;
            const int ee = e + q;
            while (ee >= nb) {           // crossed row boundary (uniform)
                if (dirty) {
                    atomicAdd(out + (size_t)cur * FDIM + foff, ax);
                    atomicAdd(out + (size_t)cur * FDIM + foff + 1, ay);
                    ax = 0.f; ay = 0.f; dirty = false;
                }
                cur++;
                nb = rowptr[cur + 1];
            }
            ax = fmaf(w[q].x, v[q][0].x, ax); ay = fmaf(w[q].x, v[q][0].y, ay);
            ax = fmaf(w[q].y, v[q][1].x, ax); ay = fmaf(w[q].y, v[q][1].y, ay);
            ax = fmaf(w[q].z, v[q][2].x, ax); ay = fmaf(w[q].z, v[q][2].y, ay);
            ax = fmaf(w[q].w, v[q][3].x, ax); ay = fmaf(w[q].w, v[q][3].y, ay);
            dirty = true;
        }
        e += gcount;
    }
    if (dirty) {
        atomicAdd(out + (size_t)cur * FDIM + foff, ax);
        atomicAdd(out + (size_t)cur * FDIM + foff + 1, ay);
    }
}

// ---------------------------------------------------------------------------
extern "C" void kernel_launch(void* const* d_in, const int* in_sizes, int n_in,
                              void* d_out, int out_size)
{
    const int*   rowptr    = (const int*)d_in[0];
    const int*   colind    = (const int*)d_in[1];
    // d_in[2] colptr, d_in[3] rowind, d_in[4] permute: unused in forward math
    const float* feat      = (const float*)d_in[5];
    const float* pseudo    = (const float*)d_in[6];
    const float* W_fc      = (const float*)d_in[7];
    const float* mu        = (const float*)d_in[8];
    const float* inv_sigma = (const float*)d_in[9];
    const float* bias      = (const float*)d_in[10];
    float*       out       = (float*)d_out;

    const int N = in_sizes[0] - 1;   // 50000
    const int E = in_sizes[1];       // 800000

    __half* nodefeat = nullptr;
    cudaGetSymbolAddress((void**)&nodefeat, g_nodefeat_h);

    // W0: one-time W pre-conversion to bf16 hi/lo
    {
        wconv_kernel<<<(KF * IN_DIM / 4 + 255) / 256, 256>>>(W_fc);
    }
    // A: dense projection feat @ W_fc^T -> g_nodefeat_h [N, 256] fp16
    {
        cudaFuncSetAttribute(gemm_mma_kernel,
                             cudaFuncAttributeMaxDynamicSharedMemorySize, GEMM_SMEM);
        dim3 grid((N + 127) / 128, KF / 128);
        gemm_mma_kernel<<<grid, 256, GEMM_SMEM>>>(feat, nodefeat, N);
    }
    // B: per-edge gaussian weights -> g_gauss [E, 4]
    {
        gauss_kernel<<<(E + 255) / 256, 256>>>(pseudo, mu, inv_sigma, E);
    }
    // I: out = bias (agg accumulates atomically on top)
    {
        const int n4 = N * (FDIM / 4);
        init_out_kernel<<<(n4 + 255) / 256, 256>>>(bias, out, N);
    }
    // C: edge-balanced weighted gather + atomic reduce -> out [N, 64]
    {
        const int warps  = (E + EPW - 1) / EPW;
        const int blocks = (warps + 7) / 8;
        agg_kernel<<<blocks, 8 * 32>>>(rowptr, colind, out, N, E);
    }
}

// round 10
// speedup vs baseline: 1.0318x; 1.0318x over previous
#include <cuda_runtime.h>
#include <cuda_bf16.h>
#include <cuda_fp16.h>
#include <cstdint>

// Problem shape (fixed for this dataset variant)
#define NNODES 50000
#define NEDGES 800000
#define IN_DIM 256
#define KHEADS 4
#define FDIM   64
#define KF     256   // KHEADS * FDIM == IN_DIM here

// Scratch (device globals: allocation-free per harness rules)
__device__ __half         g_nodefeat_h[(size_t)NNODES * KF];  // [N, 256] fp16
__device__ float4         g_gauss[NEDGES];                    // [E, 4]
__device__ int            g_dst[NEDGES];                      // [E] dest row
__device__ __nv_bfloat16  g_w_hi[KF * IN_DIM];                // W bf16 hi
__device__ __nv_bfloat16  g_w_lo[KF * IN_DIM];                // W bf16 lo

// ===========================================================================
// Helpers (family-common PTX only: ldmatrix + mma.sync, no tcgen05)
// ===========================================================================
__device__ __forceinline__ uint32_t smem_to_u32(const void* p) {
    uint32_t a;
    asm("{ .reg .u64 t; cvta.to.shared.u64 t, %1; cvt.u32.u64 %0, t; }"
        : "=r"(a) : "l"(p));
    return a;
}

__device__ __forceinline__ void ldmatrix_x4(uint32_t* r, uint32_t addr) {
    asm volatile("ldmatrix.sync.aligned.m8n8.x4.shared.b16 {%0,%1,%2,%3}, [%4];"
        : "=r"(r[0]), "=r"(r[1]), "=r"(r[2]), "=r"(r[3]) : "r"(addr));
}

__device__ __forceinline__ void mma_bf16(float* d, const uint32_t* a,
                                         uint32_t b0, uint32_t b1) {
    asm volatile(
        "mma.sync.aligned.m16n8k16.row.col.f32.bf16.bf16.f32 "
        "{%0,%1,%2,%3}, {%4,%5,%6,%7}, {%8,%9}, {%0,%1,%2,%3};"
        : "+f"(d[0]), "+f"(d[1]), "+f"(d[2]), "+f"(d[3])
        : "r"(a[0]), "r"(a[1]), "r"(a[2]), "r"(a[3]), "r"(b0), "r"(b1));
}

__device__ __forceinline__ uint32_t pack2(__nv_bfloat16 x, __nv_bfloat16 y) {
    uint16_t lo = *(uint16_t*)&x, hi = *(uint16_t*)&y;
    return (uint32_t)lo | ((uint32_t)hi << 16);
}

// ===========================================================================
// Kernel W: one-time W pre-conversion fp32 -> bf16 hi/lo (row-major layout)
// ===========================================================================
__global__ void wconv_kernel(const float* __restrict__ W)
{
    const int i = blockIdx.x * blockDim.x + threadIdx.x;   // float4 index
    if (i >= (KF * IN_DIM) / 4) return;
    const float4 v = ((const float4*)W)[i];
    const float* f = (const float*)&v;
    __nv_bfloat16 h[4], l[4];
#pragma unroll
    for (int q = 0; q < 4; q++) {
        h[q] = __float2bfloat16_rn(f[q]);
        l[q] = __float2bfloat16_rn(f[q] - __bfloat162float(h[q]));
    }
    ((uint2*)g_w_hi)[i] = make_uint2(pack2(h[0], h[1]), pack2(h[2], h[3]));
    ((uint2*)g_w_lo)[i] = make_uint2(pack2(l[0], l[1]), pack2(l[2], l[3]));
}

// ===========================================================================
// Kernel A: bf16 3x-split tensor-core GEMM  (exact R7 version, 131us best)
// ===========================================================================
#define BK 64
#define LDS_ROW 72                       // elems (144 bytes)
#define TILE_BYTES (128 * LDS_ROW * 2)   // 18432 per hi or lo
#define GEMM_SMEM (4 * TILE_BYTES)       // 73728

__global__ __launch_bounds__(256, 2)
void gemm_mma_kernel(const float* __restrict__ A, __half* __restrict__ C, int M)
{
    extern __shared__ char smem[];
    const uint32_t sb   = smem_to_u32(smem);
    const uint32_t sA_h = sb;
    const uint32_t sA_l = sb + TILE_BYTES;
    const uint32_t sW_h = sb + 2 * TILE_BYTES;
    const uint32_t sW_l = sb + 3 * TILE_BYTES;

    const int tid  = threadIdx.x;
    const int wid  = tid >> 5;
    const int lane = tid & 31;
    const int m0   = blockIdx.x * 128;
    const int bn   = blockIdx.y * 128;

    const int wm = wid & 1;      // m half (64)
    const int wn = wid >> 1;     // n quarter (32)

    float acc[4][4][4];
#pragma unroll
    for (int i = 0; i < 4; i++)
#pragma unroll
        for (int j = 0; j < 4; j++)
#pragma unroll
            for (int q = 0; q < 4; q++) acc[i][j][q] = 0.0f;

    for (int c = 0; c < IN_DIM / BK; c++) {
        const int kc = c * BK;

        __syncthreads();   // previous chunk's compute readers done

        // ---- A: load fp32, split to bf16 hi/lo, store. 128x64 = 2048 float4 ----
#pragma unroll
        for (int j = 0; j < 8; j++) {
            const int id  = tid + j * 256;
            const int row = id >> 4;
            const int c4  = (id & 15) * 4;
            const int gm  = m0 + row;

            float4 a = (gm < M)
                ? *(const float4*)(A + (size_t)gm * IN_DIM + kc + c4)
                : make_float4(0.f, 0.f, 0.f, 0.f);

            const float* av = (const float*)&a;
            __nv_bfloat16 ah[4], al[4];
#pragma unroll
            for (int q = 0; q < 4; q++) {
                ah[q] = __float2bfloat16_rn(av[q]);
                al[q] = __float2bfloat16_rn(av[q] - __bfloat162float(ah[q]));
            }
            const uint32_t off = (uint32_t)(row * (LDS_ROW * 2) + c4 * 2);
            asm volatile("st.shared.v2.b32 [%0], {%1,%2};" ::
                "r"(sA_h + off), "r"(pack2(ah[0], ah[1])), "r"(pack2(ah[2], ah[3])) : "memory");
            asm volatile("st.shared.v2.b32 [%0], {%1,%2};" ::
                "r"(sA_l + off), "r"(pack2(al[0], al[1])), "r"(pack2(al[2], al[3])) : "memory");
        }
        // ---- W: pre-converted bf16, straight 16B LDG -> STS. 128x64 bf16 ----
#pragma unroll
        for (int j = 0; j < 4; j++) {
            const int id  = tid + j * 256;        // 0..1023
            const int row = id >> 3;              // 0..127
            const int c8  = (id & 7) * 8;         // bf16 col in chunk
            const size_t goff = (size_t)(bn + row) * IN_DIM + kc + c8;
            const uint4 wh = *(const uint4*)(g_w_hi + goff);
            const uint4 wl = *(const uint4*)(g_w_lo + goff);
            const uint32_t off = (uint32_t)(row * (LDS_ROW * 2) + c8 * 2);
            asm volatile("st.shared.v4.b32 [%0], {%1,%2,%3,%4};" ::
                "r"(sW_h + off), "r"(wh.x), "r"(wh.y), "r"(wh.z), "r"(wh.w) : "memory");
            asm volatile("st.shared.v4.b32 [%0], {%1,%2,%3,%4};" ::
                "r"(sW_l + off), "r"(wl.x), "r"(wl.y), "r"(wl.z), "r"(wl.w) : "memory");
        }
        __syncthreads();

        // ---- compute: 4 k16 steps ----
#pragma unroll
        for (int ks = 0; ks < 4; ks++) {
            const int k16 = ks * 16;
            const uint32_t kbyte = (uint32_t)((k16 + (lane >> 4) * 8) * 2);

            uint32_t a_h[4][4], a_l[4][4];
#pragma unroll
            for (int mt = 0; mt < 4; mt++) {
                const uint32_t roff =
                    (uint32_t)((wm * 64 + mt * 16 + (lane & 15)) * (LDS_ROW * 2)) + kbyte;
                ldmatrix_x4(a_h[mt], sA_h + roff);
                ldmatrix_x4(a_l[mt], sA_l + roff);
            }
            uint32_t b_h[2][4], b_l[2][4];
#pragma unroll
            for (int bg = 0; bg < 2; bg++) {
                const uint32_t roff =
                    (uint32_t)((wn * 32 + bg * 16 + (lane & 15)) * (LDS_ROW * 2)) + kbyte;
                ldmatrix_x4(b_h[bg], sW_h + roff);
                ldmatrix_x4(b_l[bg], sW_l + roff);
            }

#pragma unroll
            for (int mt = 0; mt < 4; mt++) {
#pragma unroll
                for (int nt = 0; nt < 4; nt++) {
                    const int bg = nt >> 1, sel = nt & 1;
                    const uint32_t bh0 = b_h[bg][sel], bh1 = b_h[bg][sel + 2];
                    const uint32_t bl0 = b_l[bg][sel], bl1 = b_l[bg][sel + 2];
                    mma_bf16(acc[mt][nt], a_h[mt], bh0, bh1);   // hh
                    mma_bf16(acc[mt][nt], a_h[mt], bl0, bl1);   // hl
                    mma_bf16(acc[mt][nt], a_l[mt], bh0, bh1);   // lh
                }
            }
        }
    }

    // ---- epilogue: fragment -> gmem fp16 ----
    const int qrow = lane >> 2;
    const int qcol = (lane & 3) * 2;
#pragma unroll
    for (int mt = 0; mt < 4; mt++) {
        const int r0 = m0 + wm * 64 + mt * 16 + qrow;
#pragma unroll
        for (int nt = 0; nt < 4; nt++) {
            const int col = bn + wn * 32 + nt * 8 + qcol;
            if (r0 < M)
                *(__half2*)(C + (size_t)r0 * KF + col) =
                    __floats2half2_rn(acc[mt][nt][0], acc[mt][nt][1]);
            if (r0 + 8 < M)
                *(__half2*)(C + (size_t)(r0 + 8) * KF + col) =
                    __floats2half2_rn(acc[mt][nt][2], acc[mt][nt][3]);
        }
    }
}

// ---------------------------------------------------------------------------
// Kernel B: per-edge gaussian weights
// ---------------------------------------------------------------------------
__global__ void gauss_kernel(const float* __restrict__ pseudo,
                             const float* __restrict__ mu,
                             const float* __restrict__ inv_sigma,
                             int E)
{
    const int i = blockIdx.x * blockDim.x + threadIdx.x;
    if (i >= E) return;
    const float2 p = *(const float2*)(pseudo + 2 * (size_t)i);

    float w[4];
#pragma unroll
    for (int k = 0; k < 4; k++) {
        const float dx = p.x - mu[2 * k + 0];
        const float dy = p.y - mu[2 * k + 1];
        const float sx = inv_sigma[2 * k + 0];
        const float sy = inv_sigma[2 * k + 1];
        const float t  = dx * dx * sx * sx + dy * dy * sy * sy;
        w[k] = expf(-0.5f * t);
    }
    g_gauss[i] = make_float4(w[0], w[1], w[2], w[3]);
}

// ---------------------------------------------------------------------------
// Kernel D: dst[e] = destination row of edge e (warp per row, lane-strided)
// ---------------------------------------------------------------------------
__global__ void dst_kernel(const int* __restrict__ rowptr, int N)
{
    const int row  = (blockIdx.x * blockDim.x + threadIdx.x) >> 5;
    const int lane = threadIdx.x & 31;
    if (row >= N) return;
    const int e0 = rowptr[row];
    const int e1 = rowptr[row + 1];
    for (int e = e0 + lane; e < e1; e += 32)
        g_dst[e] = row;
}

// ---------------------------------------------------------------------------
// Kernel I: out[n, f] = bias[f]  (pre-fill so agg can atomically accumulate)
// ---------------------------------------------------------------------------
__global__ void init_out_kernel(const float* __restrict__ bias,
                                float* __restrict__ out, int N)
{
    const int i = blockIdx.x * blockDim.x + threadIdx.x;   // float4 index
    if (i >= N * (FDIM / 4)) return;
    ((float4*)out)[i] = ((const float4*)bias)[i & (FDIM / 4 - 1)];
}

// ---------------------------------------------------------------------------
// Kernel C: EDGE-BALANCED weighted gather + reduce, no rowptr walk.
// Each warp owns EPW consecutive edges. Row changes detected by comparing
// precomputed dst[e] (broadcast data load, no dependent pointer-chase).
// Gathers: R7's proven 4x coalesced half2 per edge, front-batched 4 deep.
// Partial sums flushed via atomicAdd into bias-prefilled out.
// ---------------------------------------------------------------------------
#define EPW 64

__global__ void agg_kernel(const int* __restrict__ colind,
                           float* __restrict__ out, int E)
{
    const int warp = (blockIdx.x * blockDim.x + threadIdx.x) >> 5;
    const int lane = threadIdx.x & 31;
    const int base = warp * EPW;
    if (base >= E) return;
    const int end = min(base + EPW, E);

    const __half* __restrict__ X = g_nodefeat_h;
    const int foff = 2 * lane;
    float ax = 0.f, ay = 0.f;
    int cur = g_dst[base];

    int e = base;
    while (e < end) {
        const int gcount = min(4, end - e);
        int    d[4];
        float4 w[4];
        float2 v[4][4];
#pragma unroll
        for (int q = 0; q < 4; q++) {
            if (q < gcount) {
                const int s = colind[e + q];
                d[q] = g_dst[e + q];
                w[q] = g_gauss[e + q];
                const __half* b = X + (size_t)s * KF + foff;
                v[q][0] = __half22float2(*(const __half2*)(b + 0));
                v[q][1] = __half22float2(*(const __half2*)(b + 64));
                v[q][2] = __half22float2(*(const __half2*)(b + 128));
                v[q][3] = __half22float2(*(const __half2*)(b + 192));
            }
        }
#pragma unroll
        for (int q = 0; q < 4; q++) {
            if (q >= gcount) break;
            if (d[q] != cur) {           // row changed: flush partial sums
                atomicAdd(out + (size_t)cur * FDIM + foff, ax);
                atomicAdd(out + (size_t)cur * FDIM + foff + 1, ay);
                ax = 0.f; ay = 0.f;
                cur = d[q];
            }
            ax = fmaf(w[q].x, v[q][0].x, ax); ay = fmaf(w[q].x, v[q][0].y, ay);
            ax = fmaf(w[q].y, v[q][1].x, ax); ay = fmaf(w[q].y, v[q][1].y, ay);
            ax = fmaf(w[q].z, v[q][2].x, ax); ay = fmaf(w[q].z, v[q][2].y, ay);
            ax = fmaf(w[q].w, v[q][3].x, ax); ay = fmaf(w[q].w, v[q][3].y, ay);
        }
        e += gcount;
    }
    atomicAdd(out + (size_t)cur * FDIM + foff, ax);
    atomicAdd(out + (size_t)cur * FDIM + foff + 1, ay);
}

// ---------------------------------------------------------------------------
extern "C" void kernel_launch(void* const* d_in, const int* in_sizes, int n_in,
                              void* d_out, int out_size)
{
    const int*   rowptr    = (const int*)d_in[0];
    const int*   colind    = (const int*)d_in[1];
    // d_in[2] colptr, d_in[3] rowind, d_in[4] permute: unused in forward math
    const float* feat      = (const float*)d_in[5];
    const float* pseudo    = (const float*)d_in[6];
    const float* W_fc      = (const float*)d_in[7];
    const float* mu        = (const float*)d_in[8];
    const float* inv_sigma = (const float*)d_in[9];
    const float* bias      = (const float*)d_in[10];
    float*       out       = (float*)d_out;

    const int N = in_sizes[0] - 1;   // 50000
    const int E = in_sizes[1];       // 800000

    __half* nodefeat = nullptr;
    cudaGetSymbolAddress((void**)&nodefeat, g_nodefeat_h);

    // W0: one-time W pre-conversion to bf16 hi/lo
    {
        wconv_kernel<<<(KF * IN_DIM / 4 + 255) / 256, 256>>>(W_fc);
    }
    // A: dense projection feat @ W_fc^T -> g_nodefeat_h [N, 256] fp16
    {
        cudaFuncSetAttribute(gemm_mma_kernel,
                             cudaFuncAttributeMaxDynamicSharedMemorySize, GEMM_SMEM);
        dim3 grid((N + 127) / 128, KF / 128);
        gemm_mma_kernel<<<grid, 256, GEMM_SMEM>>>(feat, nodefeat, N);
    }
    // B: per-edge gaussian weights -> g_gauss [E, 4]
    {
        gauss_kernel<<<(E + 255) / 256, 256>>>(pseudo, mu, inv_sigma, E);
    }
    // D: per-edge destination rows -> g_dst [E]
    {
        const int blocks = (N + 7) / 8;
        dst_kernel<<<blocks, 8 * 32>>>(rowptr, N);
    }
    // I: out = bias (agg accumulates atomically on top)
    {
        const int n4 = N * (FDIM / 4);
        init_out_kernel<<<(n4 + 255) / 256, 256>>>(bias, out, N);
    }
    // C: edge-balanced weighted gather + atomic reduce -> out [N, 64]
    {
        const int warps  = (E + EPW - 1) / EPW;
        const int blocks = (warps + 7) / 8;
        agg_kernel<<<blocks, 8 * 32>>>(colind, out, E);
    }
}

// round 11
// speedup vs baseline: 1.6474x; 1.5965x over previous
#include <cuda_runtime.h>
#include <cuda_bf16.h>
#include <cuda_fp16.h>
#include <cstdint>

// Problem shape (fixed for this dataset variant)
#define NNODES 50000
#define NEDGES 800000
#define IN_DIM 256
#define KHEADS 4
#define FDIM   64
#define KF     256   // KHEADS * FDIM == IN_DIM here

// Scratch (device globals: allocation-free per harness rules)
__device__ __half  g_nodefeat_h[(size_t)NNODES * KF];  // [N, 256] fp16
__device__ float4  g_gauss[NEDGES];                    // [E, 4]
__device__ __half  g_w_h[KF * IN_DIM];                 // W fp16

// ===========================================================================
// Helpers (family-common PTX only: ldmatrix + mma.sync, no tcgen05)
// ===========================================================================
__device__ __forceinline__ uint32_t smem_to_u32(const void* p) {
    uint32_t a;
    asm("{ .reg .u64 t; cvta.to.shared.u64 t, %1; cvt.u32.u64 %0, t; }"
        : "=r"(a) : "l"(p));
    return a;
}

__device__ __forceinline__ void ldmatrix_x4(uint32_t* r, uint32_t addr) {
    asm volatile("ldmatrix.sync.aligned.m8n8.x4.shared.b16 {%0,%1,%2,%3}, [%4];"
        : "=r"(r[0]), "=r"(r[1]), "=r"(r[2]), "=r"(r[3]) : "r"(addr));
}

__device__ __forceinline__ void mma_f16(float* d, const uint32_t* a,
                                        uint32_t b0, uint32_t b1) {
    asm volatile(
        "mma.sync.aligned.m16n8k16.row.col.f32.f16.f16.f32 "
        "{%0,%1,%2,%3}, {%4,%5,%6,%7}, {%8,%9}, {%0,%1,%2,%3};"
        : "+f"(d[0]), "+f"(d[1]), "+f"(d[2]), "+f"(d[3])
        : "r"(a[0]), "r"(a[1]), "r"(a[2]), "r"(a[3]), "r"(b0), "r"(b1));
}

__device__ __forceinline__ uint32_t pack2h(__half x, __half y) {
    uint16_t lo = *(uint16_t*)&x, hi = *(uint16_t*)&y;
    return (uint32_t)lo | ((uint32_t)hi << 16);
}

// ===========================================================================
// Kernel W: one-time W pre-conversion fp32 -> fp16 (row-major layout)
// ===========================================================================
__global__ void wconv_kernel(const float* __restrict__ W)
{
    const int i = blockIdx.x * blockDim.x + threadIdx.x;   // float4 index
    if (i >= (KF * IN_DIM) / 4) return;
    const float4 v = ((const float4*)W)[i];
    ((uint2*)g_w_h)[i] = make_uint2(
        pack2h(__float2half_rn(v.x), __float2half_rn(v.y)),
        pack2h(__float2half_rn(v.z), __float2half_rn(v.w)));
}

// ===========================================================================
// Kernel A: fp16 tensor-core GEMM  C[m,n] = sum_k A[m,k] * W[n,k]
// CTA tile 128x128, K chunked BK=64 (4 chunks). A converted in-kernel
// (fp32 -> fp16); W pre-converted. fp32 accumulation, output fp16.
// smem rows padded to 72 elems (144 B) -> conflict-free ldmatrix.
// ===========================================================================
#define BK 64
#define LDS_ROW 72                       // elems (144 bytes)
#define TILE_BYTES (128 * LDS_ROW * 2)   // 18432
#define GEMM_SMEM (2 * TILE_BYTES)       // 36864

__global__ __launch_bounds__(256, 2)
void gemm_mma_kernel(const float* __restrict__ A, __half* __restrict__ C, int M)
{
    extern __shared__ char smem[];
    const uint32_t sb = smem_to_u32(smem);
    const uint32_t sA = sb;
    const uint32_t sW = sb + TILE_BYTES;

    const int tid  = threadIdx.x;
    const int wid  = tid >> 5;
    const int lane = tid & 31;
    const int m0   = blockIdx.x * 128;
    const int bn   = blockIdx.y * 128;

    const int wm = wid & 1;      // m half (64)
    const int wn = wid >> 1;     // n quarter (32)

    float acc[4][4][4];
#pragma unroll
    for (int i = 0; i < 4; i++)
#pragma unroll
        for (int j = 0; j < 4; j++)
#pragma unroll
            for (int q = 0; q < 4; q++) acc[i][j][q] = 0.0f;

    for (int c = 0; c < IN_DIM / BK; c++) {
        const int kc = c * BK;

        __syncthreads();   // previous chunk's compute readers done

        // ---- A: load fp32, convert to fp16, store. 128x64 = 2048 float4 ----
#pragma unroll
        for (int j = 0; j < 8; j++) {
            const int id  = tid + j * 256;
            const int row = id >> 4;
            const int c4  = (id & 15) * 4;
            const int gm  = m0 + row;

            float4 a = (gm < M)
                ? *(const float4*)(A + (size_t)gm * IN_DIM + kc + c4)
                : make_float4(0.f, 0.f, 0.f, 0.f);

            const uint32_t off = (uint32_t)(row * (LDS_ROW * 2) + c4 * 2);
            asm volatile("st.shared.v2.b32 [%0], {%1,%2};" ::
                "r"(sA + off),
                "r"(pack2h(__float2half_rn(a.x), __float2half_rn(a.y))),
                "r"(pack2h(__float2half_rn(a.z), __float2half_rn(a.w))) : "memory");
        }
        // ---- W: pre-converted fp16, straight 16B LDG -> STS. 128x64 fp16 ----
#pragma unroll
        for (int j = 0; j < 4; j++) {
            const int id  = tid + j * 256;        // 0..1023
            const int row = id >> 3;              // 0..127
            const int c8  = (id & 7) * 8;         // fp16 col in chunk
            const size_t goff = (size_t)(bn + row) * IN_DIM + kc + c8;
            const uint4 wh = *(const uint4*)(g_w_h + goff);
            const uint32_t off = (uint32_t)(row * (LDS_ROW * 2) + c8 * 2);
            asm volatile("st.shared.v4.b32 [%0], {%1,%2,%3,%4};" ::
                "r"(sW + off), "r"(wh.x), "r"(wh.y), "r"(wh.z), "r"(wh.w) : "memory");
        }
        __syncthreads();

        // ---- compute: 4 k16 steps ----
#pragma unroll
        for (int ks = 0; ks < 4; ks++) {
            const int k16 = ks * 16;
            const uint32_t kbyte = (uint32_t)((k16 + (lane >> 4) * 8) * 2);

            uint32_t af[4][4];
#pragma unroll
            for (int mt = 0; mt < 4; mt++) {
                const uint32_t roff =
                    (uint32_t)((wm * 64 + mt * 16 + (lane & 15)) * (LDS_ROW * 2)) + kbyte;
                ldmatrix_x4(af[mt], sA + roff);
            }
            uint32_t bf[2][4];
#pragma unroll
            for (int bg = 0; bg < 2; bg++) {
                const uint32_t roff =
                    (uint32_t)((wn * 32 + bg * 16 + (lane & 15)) * (LDS_ROW * 2)) + kbyte;
                ldmatrix_x4(bf[bg], sW + roff);
            }

#pragma unroll
            for (int mt = 0; mt < 4; mt++) {
#pragma unroll
                for (int nt = 0; nt < 4; nt++) {
                    const int bg = nt >> 1, sel = nt & 1;
                    mma_f16(acc[mt][nt], af[mt], bf[bg][sel], bf[bg][sel + 2]);
                }
            }
        }
    }

    // ---- epilogue: fragment -> gmem fp16 ----
    const int qrow = lane >> 2;
    const int qcol = (lane & 3) * 2;
#pragma unroll
    for (int mt = 0; mt < 4; mt++) {
        const int r0 = m0 + wm * 64 + mt * 16 + qrow;
#pragma unroll
        for (int nt = 0; nt < 4; nt++) {
            const int col = bn + wn * 32 + nt * 8 + qcol;
            if (r0 < M)
                *(__half2*)(C + (size_t)r0 * KF + col) =
                    __floats2half2_rn(acc[mt][nt][0], acc[mt][nt][1]);
            if (r0 + 8 < M)
                *(__half2*)(C + (size_t)(r0 + 8) * KF + col) =
                    __floats2half2_rn(acc[mt][nt][2], acc[mt][nt][3]);
        }
    }
}

// ---------------------------------------------------------------------------
// Kernel B: per-edge gaussian weights  w[e,k] = exp(-0.5 * sum_d ((p-mu)*is)^2)
// ---------------------------------------------------------------------------
__global__ void gauss_kernel(const float* __restrict__ pseudo,
                             const float* __restrict__ mu,
                             const float* __restrict__ inv_sigma,
                             int E)
{
    const int i = blockIdx.x * blockDim.x + threadIdx.x;
    if (i >= E) return;
    const float2 p = *(const float2*)(pseudo + 2 * (size_t)i);

    float w[4];
#pragma unroll
    for (int k = 0; k < 4; k++) {
        const float dx = p.x - mu[2 * k + 0];
        const float dy = p.y - mu[2 * k + 1];
        const float sx = inv_sigma[2 * k + 0];
        const float sy = inv_sigma[2 * k + 1];
        const float t  = dx * dx * sx * sx + dy * dy * sy * sy;
        w[k] = expf(-0.5f * t);
    }
    g_gauss[i] = make_float4(w[0], w[1], w[2], w[3]);
}

// ---------------------------------------------------------------------------
// Kernel C: CSR row-parallel weighted gather + reduce. One warp per row.
// (exact R7 version — best measured agg at 55us)
// ---------------------------------------------------------------------------
__global__ void agg_kernel(const int* __restrict__ rowptr,
                           const int* __restrict__ colind,
                           const float* __restrict__ bias,
                           float* __restrict__ out, int N)
{
    const int warp = (blockIdx.x * blockDim.x + threadIdx.x) >> 5;
    const int lane = threadIdx.x & 31;
    if (warp >= N) return;

    const int e0 = rowptr[warp];
    const int e1 = rowptr[warp + 1];

    float ax = 0.f, ay = 0.f;
    const __half* __restrict__ X = g_nodefeat_h;
    const int foff = 2 * lane;

    int e = e0;
    for (; e + 2 <= e1; e += 2) {
        const int s0 = colind[e];
        const int s1 = colind[e + 1];
        const float4 w0 = g_gauss[e];
        const float4 w1 = g_gauss[e + 1];
        const __half* b0 = X + (size_t)s0 * KF + foff;
        const __half* b1 = X + (size_t)s1 * KF + foff;
        const float2 v00 = __half22float2(*(const __half2*)(b0 + 0));
        const float2 v01 = __half22float2(*(const __half2*)(b0 + 64));
        const float2 v02 = __half22float2(*(const __half2*)(b0 + 128));
        const float2 v03 = __half22float2(*(const __half2*)(b0 + 192));
        const float2 v10 = __half22float2(*(const __half2*)(b1 + 0));
        const float2 v11 = __half22float2(*(const __half2*)(b1 + 64));
        const float2 v12 = __half22float2(*(const __half2*)(b1 + 128));
        const float2 v13 = __half22float2(*(const __half2*)(b1 + 192));
        ax = fmaf(w0.x, v00.x, ax); ay = fmaf(w0.x, v00.y, ay);
        ax = fmaf(w0.y, v01.x, ax); ay = fmaf(w0.y, v01.y, ay);
        ax = fmaf(w0.z, v02.x, ax); ay = fmaf(w0.z, v02.y, ay);
        ax = fmaf(w0.w, v03.x, ax); ay = fmaf(w0.w, v03.y, ay);
        ax = fmaf(w1.x, v10.x, ax); ay = fmaf(w1.x, v10.y, ay);
        ax = fmaf(w1.y, v11.x, ax); ay = fmaf(w1.y, v11.y, ay);
        ax = fmaf(w1.z, v12.x, ax); ay = fmaf(w1.z, v12.y, ay);
        ax = fmaf(w1.w, v13.x, ax); ay = fmaf(w1.w, v13.y, ay);
    }
    if (e < e1) {
        const int s0 = colind[e];
        const float4 w0 = g_gauss[e];
        const __half* b0 = X + (size_t)s0 * KF + foff;
        const float2 v00 = __half22float2(*(const __half2*)(b0 + 0));
        const float2 v01 = __half22float2(*(const __half2*)(b0 + 64));
        const float2 v02 = __half22float2(*(const __half2*)(b0 + 128));
        const float2 v03 = __half22float2(*(const __half2*)(b0 + 192));
        ax = fmaf(w0.x, v00.x, ax); ay = fmaf(w0.x, v00.y, ay);
        ax = fmaf(w0.y, v01.x, ax); ay = fmaf(w0.y, v01.y, ay);
        ax = fmaf(w0.z, v02.x, ax); ay = fmaf(w0.z, v02.y, ay);
        ax = fmaf(w0.w, v03.x, ax); ay = fmaf(w0.w, v03.y, ay);
    }

    const float2 b = *(const float2*)(bias + foff);
    *(float2*)(out + (size_t)warp * FDIM + foff) = make_float2(ax + b.x, ay + b.y);
}

// ---------------------------------------------------------------------------
extern "C" void kernel_launch(void* const* d_in, const int* in_sizes, int n_in,
                              void* d_out, int out_size)
{
    const int*   rowptr    = (const int*)d_in[0];
    const int*   colind    = (const int*)d_in[1];
    // d_in[2] colptr, d_in[3] rowind, d_in[4] permute: unused in forward math
    const float* feat      = (const float*)d_in[5];
    const float* pseudo    = (const float*)d_in[6];
    const float* W_fc      = (const float*)d_in[7];
    const float* mu        = (const float*)d_in[8];
    const float* inv_sigma = (const float*)d_in[9];
    const float* bias      = (const float*)d_in[10];
    float*       out       = (float*)d_out;

    const int N = in_sizes[0] - 1;   // 50000
    const int E = in_sizes[1];       // 800000

    __half* nodefeat = nullptr;
    cudaGetSymbolAddress((void**)&nodefeat, g_nodefeat_h);

    // W0: one-time W pre-conversion to fp16
    {
        wconv_kernel<<<(KF * IN_DIM / 4 + 255) / 256, 256>>>(W_fc);
    }
    // A: dense projection feat @ W_fc^T -> g_nodefeat_h [N, 256] fp16
    {
        cudaFuncSetAttribute(gemm_mma_kernel,
                             cudaFuncAttributeMaxDynamicSharedMemorySize, GEMM_SMEM);
        dim3 grid((N + 127) / 128, KF / 128);
        gemm_mma_kernel<<<grid, 256, GEMM_SMEM>>>(feat, nodefeat, N);
    }
    // B: per-edge gaussian weights -> g_gauss [E, 4]
    {
        gauss_kernel<<<(E + 255) / 256, 256>>>(pseudo, mu, inv_sigma, E);
    }
    // C: row-parallel weighted gather + reduce + bias -> out [N, 64]
    {
        const int warps_per_block = 8;
        const int blocks = (N + warps_per_block - 1) / warps_per_block;
        agg_kernel<<<blocks, warps_per_block * 32>>>(rowptr, colind, bias, out, N);
    }
}

// round 12
// speedup vs baseline: 1.7001x; 1.0320x over previous
#include <cuda_runtime.h>
#include <cuda_bf16.h>
#include <cuda_fp16.h>
#include <cstdint>

// Problem shape (fixed for this dataset variant)
#define NNODES 50000
#define NEDGES 800000
#define IN_DIM 256
#define KHEADS 4
#define FDIM   64
#define KF     256   // KHEADS * FDIM == IN_DIM here

// Scratch (device globals: allocation-free per harness rules)
__device__ __half  g_nodefeat_h[(size_t)NNODES * KF];  // [N, 256] fp16
__device__ float4  g_gauss[NEDGES];                    // [E, 4]
__device__ __half  g_w_h[KF * IN_DIM];                 // W fp16

// ===========================================================================
// Helpers (family-common PTX only: ldmatrix + mma.sync, no tcgen05)
// ===========================================================================
__device__ __forceinline__ uint32_t smem_to_u32(const void* p) {
    uint32_t a;
    asm("{ .reg .u64 t; cvta.to.shared.u64 t, %1; cvt.u32.u64 %0, t; }"
        : "=r"(a) : "l"(p));
    return a;
}

__device__ __forceinline__ void ldmatrix_x4(uint32_t* r, uint32_t addr) {
    asm volatile("ldmatrix.sync.aligned.m8n8.x4.shared.b16 {%0,%1,%2,%3}, [%4];"
        : "=r"(r[0]), "=r"(r[1]), "=r"(r[2]), "=r"(r[3]) : "r"(addr));
}

__device__ __forceinline__ void mma_f16(float* d, const uint32_t* a,
                                        uint32_t b0, uint32_t b1) {
    asm volatile(
        "mma.sync.aligned.m16n8k16.row.col.f32.f16.f16.f32 "
        "{%0,%1,%2,%3}, {%4,%5,%6,%7}, {%8,%9}, {%0,%1,%2,%3};"
        : "+f"(d[0]), "+f"(d[1]), "+f"(d[2]), "+f"(d[3])
        : "r"(a[0]), "r"(a[1]), "r"(a[2]), "r"(a[3]), "r"(b0), "r"(b1));
}

__device__ __forceinline__ uint32_t pack2h(__half x, __half y) {
    uint16_t lo = *(uint16_t*)&x, hi = *(uint16_t*)&y;
    return (uint32_t)lo | ((uint32_t)hi << 16);
}

// ===========================================================================
// Kernel W: one-time W pre-conversion fp32 -> fp16 (row-major layout)
// ===========================================================================
__global__ void wconv_kernel(const float* __restrict__ W)
{
    const int i = blockIdx.x * blockDim.x + threadIdx.x;   // float4 index
    if (i >= (KF * IN_DIM) / 4) return;
    const float4 v = ((const float4*)W)[i];
    ((uint2*)g_w_h)[i] = make_uint2(
        pack2h(__float2half_rn(v.x), __float2half_rn(v.y)),
        pack2h(__float2half_rn(v.z), __float2half_rn(v.w)));
}

// ===========================================================================
// Kernel A: fp16 tensor-core GEMM, software-pipelined.
// CTA tile 128(M) x 128(N), K = 256 in 8 chunks of BK=32.
// W tile (128 x 256 fp16) resident in smem (loaded once in prologue).
// A double-buffered in smem; next chunk's LDGs issued before the barrier so
// gmem latency overlaps compute. One __syncthreads per iteration.
// ===========================================================================
#define BK2     32
#define A_ROW_B 80                      // 32 fp16 + 8 pad (bytes)
#define A_BUF_B (128 * A_ROW_B)         // 10240
#define W_ROW_B 528                     // 256 fp16 + 8 pad (bytes)
#define W_BUF_B (128 * W_ROW_B)         // 67584
#define GEMM_SMEM (2 * A_BUF_B + W_BUF_B)   // 88064

__global__ __launch_bounds__(256, 2)
void gemm_mma_kernel(const float* __restrict__ A, __half* __restrict__ C, int M)
{
    extern __shared__ char smem[];
    const uint32_t sb  = smem_to_u32(smem);
    const uint32_t sW  = sb + 2 * A_BUF_B;

    const int tid  = threadIdx.x;
    const int wid  = tid >> 5;
    const int lane = tid & 31;
    const int m0   = blockIdx.x * 128;
    const int bn   = blockIdx.y * 128;

    const int wm = wid & 1;      // m half (64)
    const int wn = wid >> 1;     // n quarter (32)

    // ---- prologue: W tile 128x256 fp16 -> smem (once) ----
#pragma unroll
    for (int j = 0; j < 16; j++) {
        const int id  = tid + j * 256;     // 0..4095
        const int row = id >> 5;           // 0..127
        const int c8  = (id & 31) * 8;     // fp16 col
        const uint4 w = *(const uint4*)(g_w_h + (size_t)(bn + row) * IN_DIM + c8);
        *(uint4*)(smem + 2 * A_BUF_B + row * W_ROW_B + c8 * 2) = w;
    }

    float acc[4][4][4];
#pragma unroll
    for (int i = 0; i < 4; i++)
#pragma unroll
        for (int j = 0; j < 4; j++)
#pragma unroll
            for (int q = 0; q < 4; q++) acc[i][j][q] = 0.0f;

    // A load mapping: 1024 float4 per chunk; 4 per thread.
    const int arow = tid >> 1;                  // unused helper removed
    (void)arow;

    float4 pref[4];
#pragma unroll
    for (int j = 0; j < 4; j++) {               // prefetch chunk 0
        const int id  = tid + j * 256;
        const int row = id >> 3;
        const int c4  = (id & 7) * 4;
        const int gm  = m0 + row;
        pref[j] = (gm < M)
            ? *(const float4*)(A + (size_t)gm * IN_DIM + 0 * BK2 + c4)
            : make_float4(0.f, 0.f, 0.f, 0.f);
    }

    for (int c = 0; c < IN_DIM / BK2; c++) {
        const uint32_t abuf = sb + (uint32_t)(c & 1) * A_BUF_B;

        // ---- STS chunk c (convert fp32 regs -> fp16 smem) ----
#pragma unroll
        for (int j = 0; j < 4; j++) {
            const int id  = tid + j * 256;
            const int row = id >> 3;
            const int c4  = (id & 7) * 4;
            const float4 a = pref[j];
            asm volatile("st.shared.v2.b32 [%0], {%1,%2};" ::
                "r"(abuf + (uint32_t)(row * A_ROW_B + c4 * 2)),
                "r"(pack2h(__float2half_rn(a.x), __float2half_rn(a.y))),
                "r"(pack2h(__float2half_rn(a.z), __float2half_rn(a.w))) : "memory");
        }
        // ---- prefetch chunk c+1 (overlaps with compute below) ----
        if (c < IN_DIM / BK2 - 1) {
#pragma unroll
            for (int j = 0; j < 4; j++) {
                const int id  = tid + j * 256;
                const int row = id >> 3;
                const int c4  = (id & 7) * 4;
                const int gm  = m0 + row;
                pref[j] = (gm < M)
                    ? *(const float4*)(A + (size_t)gm * IN_DIM + (c + 1) * BK2 + c4)
                    : make_float4(0.f, 0.f, 0.f, 0.f);
            }
        }
        __syncthreads();

        // ---- compute chunk c: 2 k16 steps ----
#pragma unroll
        for (int ks = 0; ks < 2; ks++) {
            const uint32_t kbyte = (uint32_t)((ks * 16 + (lane >> 4) * 8) * 2);

            uint32_t af[4][4];
#pragma unroll
            for (int mt = 0; mt < 4; mt++) {
                const uint32_t roff =
                    (uint32_t)((wm * 64 + mt * 16 + (lane & 15)) * A_ROW_B) + kbyte;
                ldmatrix_x4(af[mt], abuf + roff);
            }
            uint32_t bf[2][4];
            const uint32_t wkoff = (uint32_t)(c * BK2 * 2) + kbyte;
#pragma unroll
            for (int bg = 0; bg < 2; bg++) {
                const uint32_t roff =
                    (uint32_t)((wn * 32 + bg * 16 + (lane & 15)) * W_ROW_B) + wkoff;
                ldmatrix_x4(bf[bg], sW + roff);
            }

#pragma unroll
            for (int mt = 0; mt < 4; mt++) {
#pragma unroll
                for (int nt = 0; nt < 4; nt++) {
                    const int bg = nt >> 1, sel = nt & 1;
                    mma_f16(acc[mt][nt], af[mt], bf[bg][sel], bf[bg][sel + 2]);
                }
            }
        }
    }

    // ---- epilogue: fragment -> gmem fp16 ----
    const int qrow = lane >> 2;
    const int qcol = (lane & 3) * 2;
#pragma unroll
    for (int mt = 0; mt < 4; mt++) {
        const int r0 = m0 + wm * 64 + mt * 16 + qrow;
#pragma unroll
        for (int nt = 0; nt < 4; nt++) {
            const int col = bn + wn * 32 + nt * 8 + qcol;
            if (r0 < M)
                *(__half2*)(C + (size_t)r0 * KF + col) =
                    __floats2half2_rn(acc[mt][nt][0], acc[mt][nt][1]);
            if (r0 + 8 < M)
                *(__half2*)(C + (size_t)(r0 + 8) * KF + col) =
                    __floats2half2_rn(acc[mt][nt][2], acc[mt][nt][3]);
        }
    }
}

// ---------------------------------------------------------------------------
// Kernel B: per-edge gaussian weights  (exact R11 version)
// ---------------------------------------------------------------------------
__global__ void gauss_kernel(const float* __restrict__ pseudo,
                             const float* __restrict__ mu,
                             const float* __restrict__ inv_sigma,
                             int E)
{
    const int i = blockIdx.x * blockDim.x + threadIdx.x;
    if (i >= E) return;
    const float2 p = *(const float2*)(pseudo + 2 * (size_t)i);

    float w[4];
#pragma unroll
    for (int k = 0; k < 4; k++) {
        const float dx = p.x - mu[2 * k + 0];
        const float dy = p.y - mu[2 * k + 1];
        const float sx = inv_sigma[2 * k + 0];
        const float sy = inv_sigma[2 * k + 1];
        const float t  = dx * dx * sx * sx + dy * dy * sy * sy;
        w[k] = expf(-0.5f * t);
    }
    g_gauss[i] = make_float4(w[0], w[1], w[2], w[3]);
}

// ---------------------------------------------------------------------------
// Kernel C: CSR row-parallel weighted gather + reduce. One warp per row.
// (exact R11 version — best measured agg at 55us)
// ---------------------------------------------------------------------------
__global__ void agg_kernel(const int* __restrict__ rowptr,
                           const int* __restrict__ colind,
                           const float* __restrict__ bias,
                           float* __restrict__ out, int N)
{
    const int warp = (blockIdx.x * blockDim.x + threadIdx.x) >> 5;
    const int lane = threadIdx.x & 31;
    if (warp >= N) return;

    const int e0 = rowptr[warp];
    const int e1 = rowptr[warp + 1];

    float ax = 0.f, ay = 0.f;
    const __half* __restrict__ X = g_nodefeat_h;
    const int foff = 2 * lane;

    int e = e0;
    for (; e + 2 <= e1; e += 2) {
        const int s0 = colind[e];
        const int s1 = colind[e + 1];
        const float4 w0 = g_gauss[e];
        const float4 w1 = g_gauss[e + 1];
        const __half* b0 = X + (size_t)s0 * KF + foff;
        const __half* b1 = X + (size_t)s1 * KF + foff;
        const float2 v00 = __half22float2(*(const __half2*)(b0 + 0));
        const float2 v01 = __half22float2(*(const __half2*)(b0 + 64));
        const float2 v02 = __half22float2(*(const __half2*)(b0 + 128));
        const float2 v03 = __half22float2(*(const __half2*)(b0 + 192));
        const float2 v10 = __half22float2(*(const __half2*)(b1 + 0));
        const float2 v11 = __half22float2(*(const __half2*)(b1 + 64));
        const float2 v12 = __half22float2(*(const __half2*)(b1 + 128));
        const float2 v13 = __half22float2(*(const __half2*)(b1 + 192));
        ax = fmaf(w0.x, v00.x, ax); ay = fmaf(w0.x, v00.y, ay);
        ax = fmaf(w0.y, v01.x, ax); ay = fmaf(w0.y, v01.y, ay);
        ax = fmaf(w0.z, v02.x, ax); ay = fmaf(w0.z, v02.y, ay);
        ax = fmaf(w0.w, v03.x, ax); ay = fmaf(w0.w, v03.y, ay);
        ax = fmaf(w1.x, v10.x, ax); ay = fmaf(w1.x, v10.y, ay);
        ax = fmaf(w1.y, v11.x, ax); ay = fmaf(w1.y, v11.y, ay);
        ax = fmaf(w1.z, v12.x, ax); ay = fmaf(w1.z, v12.y, ay);
        ax = fmaf(w1.w, v13.x, ax); ay = fmaf(w1.w, v13.y, ay);
    }
    if (e < e1) {
        const int s0 = colind[e];
        const float4 w0 = g_gauss[e];
        const __half* b0 = X + (size_t)s0 * KF + foff;
        const float2 v00 = __half22float2(*(const __half2*)(b0 + 0));
        const float2 v01 = __half22float2(*(const __half2*)(b0 + 64));
        const float2 v02 = __half22float2(*(const __half2*)(b0 + 128));
        const float2 v03 = __half22float2(*(const __half2*)(b0 + 192));
        ax = fmaf(w0.x, v00.x, ax); ay = fmaf(w0.x, v00.y, ay);
        ax = fmaf(w0.y, v01.x, ax); ay = fmaf(w0.y, v01.y, ay);
        ax = fmaf(w0.z, v02.x, ax); ay = fmaf(w0.z, v02.y, ay);
        ax = fmaf(w0.w, v03.x, ax); ay = fmaf(w0.w, v03.y, ay);
    }

    const float2 b = *(const float2*)(bias + foff);
    *(float2*)(out + (size_t)warp * FDIM + foff) = make_float2(ax + b.x, ay + b.y);
}

// ---------------------------------------------------------------------------
extern "C" void kernel_launch(void* const* d_in, const int* in_sizes, int n_in,
                              void* d_out, int out_size)
{
    const int*   rowptr    = (const int*)d_in[0];
    const int*   colind    = (const int*)d_in[1];
    // d_in[2] colptr, d_in[3] rowind, d_in[4] permute: unused in forward math
    const float* feat      = (const float*)d_in[5];
    const float* pseudo    = (const float*)d_in[6];
    const float* W_fc      = (const float*)d_in[7];
    const float* mu        = (const float*)d_in[8];
    const float* inv_sigma = (const float*)d_in[9];
    const float* bias      = (const float*)d_in[10];
    float*       out       = (float*)d_out;

    const int N = in_sizes[0] - 1;   // 50000
    const int E = in_sizes[1];       // 800000

    __half* nodefeat = nullptr;
    cudaGetSymbolAddress((void**)&nodefeat, g_nodefeat_h);

    // W0: one-time W pre-conversion to fp16
    {
        wconv_kernel<<<(KF * IN_DIM / 4 + 255) / 256, 256>>>(W_fc);
    }
    // A: dense projection feat @ W_fc^T -> g_nodefeat_h [N, 256] fp16
    {
        cudaFuncSetAttribute(gemm_mma_kernel,
                             cudaFuncAttributeMaxDynamicSharedMemorySize, GEMM_SMEM);
        dim3 grid((N + 127) / 128, KF / 128);
        gemm_mma_kernel<<<grid, 256, GEMM_SMEM>>>(feat, nodefeat, N);
    }
    // B: per-edge gaussian weights -> g_gauss [E, 4]
    {
        gauss_kernel<<<(E + 255) / 256, 256>>>(pseudo, mu, inv_sigma, E);
    }
    // C: row-parallel weighted gather + reduce + bias -> out [N, 64]
    {
        const int warps_per_block = 8;
        const int blocks = (N + warps_per_block - 1) / warps_per_block;
        agg_kernel<<<blocks, warps_per_block * 32>>>(rowptr, colind, bias, out, N);
    }
}

// round 13
// speedup vs baseline: 1.7046x; 1.0026x over previous
#include <cuda_runtime.h>
#include <cuda_bf16.h>
#include <cuda_fp16.h>
#include <cstdint>

// Problem shape (fixed for this dataset variant)
#define NNODES 50000
#define NEDGES 800000
#define IN_DIM 256
#define KHEADS 4
#define FDIM   64
#define KF     256   // KHEADS * FDIM == IN_DIM here

// Scratch (device globals: allocation-free per harness rules)
__device__ __half  g_nodefeat_h[(size_t)NNODES * KF];  // [N, 256] fp16
__device__ uint2   g_gauss_h[NEDGES];                  // [E, 4] fp16 weights
__device__ __half  g_w_h[KF * IN_DIM];                 // W fp16

// ===========================================================================
// Helpers (family-common PTX only: ldmatrix + mma.sync, no tcgen05)
// ===========================================================================
__device__ __forceinline__ uint32_t smem_to_u32(const void* p) {
    uint32_t a;
    asm("{ .reg .u64 t; cvta.to.shared.u64 t, %1; cvt.u32.u64 %0, t; }"
        : "=r"(a) : "l"(p));
    return a;
}

__device__ __forceinline__ void ldmatrix_x4(uint32_t* r, uint32_t addr) {
    asm volatile("ldmatrix.sync.aligned.m8n8.x4.shared.b16 {%0,%1,%2,%3}, [%4];"
        : "=r"(r[0]), "=r"(r[1]), "=r"(r[2]), "=r"(r[3]) : "r"(addr));
}

__device__ __forceinline__ void mma_f16(float* d, const uint32_t* a,
                                        uint32_t b0, uint32_t b1) {
    asm volatile(
        "mma.sync.aligned.m16n8k16.row.col.f32.f16.f16.f32 "
        "{%0,%1,%2,%3}, {%4,%5,%6,%7}, {%8,%9}, {%0,%1,%2,%3};"
        : "+f"(d[0]), "+f"(d[1]), "+f"(d[2]), "+f"(d[3])
        : "r"(a[0]), "r"(a[1]), "r"(a[2]), "r"(a[3]), "r"(b0), "r"(b1));
}

__device__ __forceinline__ uint32_t pack2h(__half x, __half y) {
    uint16_t lo = *(uint16_t*)&x, hi = *(uint16_t*)&y;
    return (uint32_t)lo | ((uint32_t)hi << 16);
}

// ===========================================================================
// Kernel W: one-time W pre-conversion fp32 -> fp16 (row-major layout)
// ===========================================================================
__global__ void wconv_kernel(const float* __restrict__ W)
{
    const int i = blockIdx.x * blockDim.x + threadIdx.x;   // float4 index
    if (i >= (KF * IN_DIM) / 4) return;
    const float4 v = ((const float4*)W)[i];
    ((uint2*)g_w_h)[i] = make_uint2(
        pack2h(__float2half_rn(v.x), __float2half_rn(v.y)),
        pack2h(__float2half_rn(v.z), __float2half_rn(v.w)));
}

// ===========================================================================
// Kernel A: fp16 tensor-core GEMM, software-pipelined (exact R12 version).
// ===========================================================================
#define BK2     32
#define A_ROW_B 80                      // 32 fp16 + 8 pad (bytes)
#define A_BUF_B (128 * A_ROW_B)         // 10240
#define W_ROW_B 528                     // 256 fp16 + 8 pad (bytes)
#define W_BUF_B (128 * W_ROW_B)         // 67584
#define GEMM_SMEM (2 * A_BUF_B + W_BUF_B)   // 88064

__global__ __launch_bounds__(256, 2)
void gemm_mma_kernel(const float* __restrict__ A, __half* __restrict__ C, int M)
{
    extern __shared__ char smem[];
    const uint32_t sb  = smem_to_u32(smem);
    const uint32_t sW  = sb + 2 * A_BUF_B;

    const int tid  = threadIdx.x;
    const int wid  = tid >> 5;
    const int lane = tid & 31;
    const int m0   = blockIdx.x * 128;
    const int bn   = blockIdx.y * 128;

    const int wm = wid & 1;      // m half (64)
    const int wn = wid >> 1;     // n quarter (32)

    // ---- prologue: W tile 128x256 fp16 -> smem (once) ----
#pragma unroll
    for (int j = 0; j < 16; j++) {
        const int id  = tid + j * 256;     // 0..4095
        const int row = id >> 5;           // 0..127
        const int c8  = (id & 31) * 8;     // fp16 col
        const uint4 w = *(const uint4*)(g_w_h + (size_t)(bn + row) * IN_DIM + c8);
        *(uint4*)(smem + 2 * A_BUF_B + row * W_ROW_B + c8 * 2) = w;
    }

    float acc[4][4][4];
#pragma unroll
    for (int i = 0; i < 4; i++)
#pragma unroll
        for (int j = 0; j < 4; j++)
#pragma unroll
            for (int q = 0; q < 4; q++) acc[i][j][q] = 0.0f;

    float4 pref[4];
#pragma unroll
    for (int j = 0; j < 4; j++) {               // prefetch chunk 0
        const int id  = tid + j * 256;
        const int row = id >> 3;
        const int c4  = (id & 7) * 4;
        const int gm  = m0 + row;
        pref[j] = (gm < M)
            ? *(const float4*)(A + (size_t)gm * IN_DIM + 0 * BK2 + c4)
            : make_float4(0.f, 0.f, 0.f, 0.f);
    }

    for (int c = 0; c < IN_DIM / BK2; c++) {
        const uint32_t abuf = sb + (uint32_t)(c & 1) * A_BUF_B;

        // ---- STS chunk c (convert fp32 regs -> fp16 smem) ----
#pragma unroll
        for (int j = 0; j < 4; j++) {
            const int id  = tid + j * 256;
            const int row = id >> 3;
            const int c4  = (id & 7) * 4;
            const float4 a = pref[j];
            asm volatile("st.shared.v2.b32 [%0], {%1,%2};" ::
                "r"(abuf + (uint32_t)(row * A_ROW_B + c4 * 2)),
                "r"(pack2h(__float2half_rn(a.x), __float2half_rn(a.y))),
                "r"(pack2h(__float2half_rn(a.z), __float2half_rn(a.w))) : "memory");
        }
        // ---- prefetch chunk c+1 (overlaps with compute below) ----
        if (c < IN_DIM / BK2 - 1) {
#pragma unroll
            for (int j = 0; j < 4; j++) {
                const int id  = tid + j * 256;
                const int row = id >> 3;
                const int c4  = (id & 7) * 4;
                const int gm  = m0 + row;
                pref[j] = (gm < M)
                    ? *(const float4*)(A + (size_t)gm * IN_DIM + (c + 1) * BK2 + c4)
                    : make_float4(0.f, 0.f, 0.f, 0.f);
            }
        }
        __syncthreads();

        // ---- compute chunk c: 2 k16 steps ----
#pragma unroll
        for (int ks = 0; ks < 2; ks++) {
            const uint32_t kbyte = (uint32_t)((ks * 16 + (lane >> 4) * 8) * 2);

            uint32_t af[4][4];
#pragma unroll
            for (int mt = 0; mt < 4; mt++) {
                const uint32_t roff =
                    (uint32_t)((wm * 64 + mt * 16 + (lane & 15)) * A_ROW_B) + kbyte;
                ldmatrix_x4(af[mt], abuf + roff);
            }
            uint32_t bf[2][4];
            const uint32_t wkoff = (uint32_t)(c * BK2 * 2) + kbyte;
#pragma unroll
            for (int bg = 0; bg < 2; bg++) {
                const uint32_t roff =
                    (uint32_t)((wn * 32 + bg * 16 + (lane & 15)) * W_ROW_B) + wkoff;
                ldmatrix_x4(bf[bg], sW + roff);
            }

#pragma unroll
            for (int mt = 0; mt < 4; mt++) {
#pragma unroll
                for (int nt = 0; nt < 4; nt++) {
                    const int bg = nt >> 1, sel = nt & 1;
                    mma_f16(acc[mt][nt], af[mt], bf[bg][sel], bf[bg][sel + 2]);
                }
            }
        }
    }

    // ---- epilogue: fragment -> gmem fp16 ----
    const int qrow = lane >> 2;
    const int qcol = (lane & 3) * 2;
#pragma unroll
    for (int mt = 0; mt < 4; mt++) {
        const int r0 = m0 + wm * 64 + mt * 16 + qrow;
#pragma unroll
        for (int nt = 0; nt < 4; nt++) {
            const int col = bn + wn * 32 + nt * 8 + qcol;
            if (r0 < M)
                *(__half2*)(C + (size_t)r0 * KF + col) =
                    __floats2half2_rn(acc[mt][nt][0], acc[mt][nt][1]);
            if (r0 + 8 < M)
                *(__half2*)(C + (size_t)(r0 + 8) * KF + col) =
                    __floats2half2_rn(acc[mt][nt][2], acc[mt][nt][3]);
        }
    }
}

// ---------------------------------------------------------------------------
// Kernel B: per-edge gaussian weights -> fp16x4 (8 B per edge)
// ---------------------------------------------------------------------------
__global__ void gauss_kernel(const float* __restrict__ pseudo,
                             const float* __restrict__ mu,
                             const float* __restrict__ inv_sigma,
                             int E)
{
    const int i = blockIdx.x * blockDim.x + threadIdx.x;
    if (i >= E) return;
    const float2 p = *(const float2*)(pseudo + 2 * (size_t)i);

    float w[4];
#pragma unroll
    for (int k = 0; k < 4; k++) {
        const float dx = p.x - mu[2 * k + 0];
        const float dy = p.y - mu[2 * k + 1];
        const float sx = inv_sigma[2 * k + 0];
        const float sy = inv_sigma[2 * k + 1];
        const float t  = dx * dx * sx * sx + dy * dy * sy * sy;
        w[k] = expf(-0.5f * t);
    }
    g_gauss_h[i] = make_uint2(
        pack2h(__float2half_rn(w[0]), __float2half_rn(w[1])),
        pack2h(__float2half_rn(w[2]), __float2half_rn(w[3])));
}

// ---------------------------------------------------------------------------
// Kernel C: CSR row-parallel weighted gather + reduce. One warp per row.
// Inner loop identical to the proven R7/R11 kernel; weights now fp16x4.
// Launched with 64-thread blocks (2 warps) so block retirement isn't gated
// by the slowest of 8 rows -> higher achieved occupancy.
// ---------------------------------------------------------------------------
__global__ void agg_kernel(const int* __restrict__ rowptr,
                           const int* __restrict__ colind,
                           const float* __restrict__ bias,
                           float* __restrict__ out, int N)
{
    const int warp = (blockIdx.x * blockDim.x + threadIdx.x) >> 5;
    const int lane = threadIdx.x & 31;
    if (warp >= N) return;

    const int e0 = rowptr[warp];
    const int e1 = rowptr[warp + 1];

    float ax = 0.f, ay = 0.f;
    const __half* __restrict__ X = g_nodefeat_h;
    const int foff = 2 * lane;

    int e = e0;
    for (; e + 2 <= e1; e += 2) {
        const int s0 = colind[e];
        const int s1 = colind[e + 1];
        const uint2 wp0 = g_gauss_h[e];
        const uint2 wp1 = g_gauss_h[e + 1];
        const __half* b0 = X + (size_t)s0 * KF + foff;
        const __half* b1 = X + (size_t)s1 * KF + foff;
        const float2 v00 = __half22float2(*(const __half2*)(b0 + 0));
        const float2 v01 = __half22float2(*(const __half2*)(b0 + 64));
        const float2 v02 = __half22float2(*(const __half2*)(b0 + 128));
        const float2 v03 = __half22float2(*(const __half2*)(b0 + 192));
        const float2 v10 = __half22float2(*(const __half2*)(b1 + 0));
        const float2 v11 = __half22float2(*(const __half2*)(b1 + 64));
        const float2 v12 = __half22float2(*(const __half2*)(b1 + 128));
        const float2 v13 = __half22float2(*(const __half2*)(b1 + 192));
        const float2 w0a = __half22float2(*(const __half2*)&wp0.x);
        const float2 w0b = __half22float2(*(const __half2*)&wp0.y);
        const float2 w1a = __half22float2(*(const __half2*)&wp1.x);
        const float2 w1b = __half22float2(*(const __half2*)&wp1.y);
        ax = fmaf(w0a.x, v00.x, ax); ay = fmaf(w0a.x, v00.y, ay);
        ax = fmaf(w0a.y, v01.x, ax); ay = fmaf(w0a.y, v01.y, ay);
        ax = fmaf(w0b.x, v02.x, ax); ay = fmaf(w0b.x, v02.y, ay);
        ax = fmaf(w0b.y, v03.x, ax); ay = fmaf(w0b.y, v03.y, ay);
        ax = fmaf(w1a.x, v10.x, ax); ay = fmaf(w1a.x, v10.y, ay);
        ax = fmaf(w1a.y, v11.x, ax); ay = fmaf(w1a.y, v11.y, ay);
        ax = fmaf(w1b.x, v12.x, ax); ay = fmaf(w1b.x, v12.y, ay);
        ax = fmaf(w1b.y, v13.x, ax); ay = fmaf(w1b.y, v13.y, ay);
    }
    if (e < e1) {
        const int s0 = colind[e];
        const uint2 wp0 = g_gauss_h[e];
        const __half* b0 = X + (size_t)s0 * KF + foff;
        const float2 v00 = __half22float2(*(const __half2*)(b0 + 0));
        const float2 v01 = __half22float2(*(const __half2*)(b0 + 64));
        const float2 v02 = __half22float2(*(const __half2*)(b0 + 128));
        const float2 v03 = __half22float2(*(const __half2*)(b0 + 192));
        const float2 w0a = __half22float2(*(const __half2*)&wp0.x);
        const float2 w0b = __half22float2(*(const __half2*)&wp0.y);
        ax = fmaf(w0a.x, v00.x, ax); ay = fmaf(w0a.x, v00.y, ay);
        ax = fmaf(w0a.y, v01.x, ax); ay = fmaf(w0a.y, v01.y, ay);
        ax = fmaf(w0b.x, v02.x, ax); ay = fmaf(w0b.x, v02.y, ay);
        ax = fmaf(w0b.y, v03.x, ax); ay = fmaf(w0b.y, v03.y, ay);
    }

    const float2 b = *(const float2*)(bias + foff);
    *(float2*)(out + (size_t)warp * FDIM + foff) = make_float2(ax + b.x, ay + b.y);
}

// ---------------------------------------------------------------------------
extern "C" void kernel_launch(void* const* d_in, const int* in_sizes, int n_in,
                              void* d_out, int out_size)
{
    const int*   rowptr    = (const int*)d_in[0];
    const int*   colind    = (const int*)d_in[1];
    // d_in[2] colptr, d_in[3] rowind, d_in[4] permute: unused in forward math
    const float* feat      = (const float*)d_in[5];
    const float* pseudo    = (const float*)d_in[6];
    const float* W_fc      = (const float*)d_in[7];
    const float* mu        = (const float*)d_in[8];
    const float* inv_sigma = (const float*)d_in[9];
    const float* bias      = (const float*)d_in[10];
    float*       out       = (float*)d_out;

    const int N = in_sizes[0] - 1;   // 50000
    const int E = in_sizes[1];       // 800000

    __half* nodefeat = nullptr;
    cudaGetSymbolAddress((void**)&nodefeat, g_nodefeat_h);

    // W0: one-time W pre-conversion to fp16
    {
        wconv_kernel<<<(KF * IN_DIM / 4 + 255) / 256, 256>>>(W_fc);
    }
    // A: dense projection feat @ W_fc^T -> g_nodefeat_h [N, 256] fp16
    {
        cudaFuncSetAttribute(gemm_mma_kernel,
                             cudaFuncAttributeMaxDynamicSharedMemorySize, GEMM_SMEM);
        dim3 grid((N + 127) / 128, KF / 128);
        gemm_mma_kernel<<<grid, 256, GEMM_SMEM>>>(feat, nodefeat, N);
    }
    // B: per-edge gaussian weights -> g_gauss_h [E, 4] fp16
    {
        gauss_kernel<<<(E + 255) / 256, 256>>>(pseudo, mu, inv_sigma, E);
    }
    // C: row-parallel weighted gather + reduce + bias -> out [N, 64]
    //    2 warps per block: fine-grained block retirement.
    {
        const int warps_per_block = 2;
        const int blocks = (N + warps_per_block - 1) / warps_per_block;
        agg_kernel<<<blocks, warps_per_block * 32>>>(rowptr, colind, bias, out, N);
    }
}